// round 14
// baseline (speedup 1.0000x reference)
#include <cuda_runtime.h>
#include <cuda_bf16.h>
#include <cstdint>

// ---------------------------------------------------------------------------
// CustomBLIP: sigmoid( relu( bilinear(img_n, txt_n; Wp) + bp ) @ Wc^T + bc )
// Core: feats[b,k] = sum_ij (img[b,i]*txt[b,j]) * Wp[k, i*512+j]
//   -> GEMM C[256,512] = A[256,262144] x Wp^T, A generated on the fly.
// R13 = R12 + instruction diet: single img register set reloaded post-compute
//      (kills 8 MOV/iter, -8 regs), inner loop unrolled x2 for scheduling.
//      4 independent warp-pairs, pair-local 5-stage cp.async rings, 64-thread
//      named barriers, txt in regs per j-block. 100KB smem, 2 CTAs/SM.
// ---------------------------------------------------------------------------

#define B_SZ   256
#define M_DIM  512
#define KIJ    (512 * 512)          // 262144
#define ITERS  8192                 // chunks of 32 ij
#define BM     128
#define BN     128
#define SPLITS 37                   // 37*4*2 = 296 CTAs = 2/SM

#define NSTG    5                   // stages per pair ring
#define BSTRP   40                  // pair stage row stride in fp32 (32+8 pad)
#define STGP    (32 * BSTRP)        // 1280 u32 per stage
#define PAIRU   (NSTG * STGP)       // 6400 u32 per pair

#define SM_U32_TOT (4 * PAIRU)      // 25600
#define SM_BYTES   (SM_U32_TOT * 4) // 102400 -> 2 CTAs/SM

// -------------------------------- scratch ---------------------------------
__device__ float                        g_pre[2 * B_SZ * M_DIM];
__device__ uint32_t                     g_imgu[M_DIM * B_SZ];  // [i][b] bf16x2
__device__ __align__(16) __nv_bfloat16  g_txtb[B_SZ * M_DIM];  // [b][j]
__device__ float                        g_feats[B_SZ * M_DIM];

// -------------------------------- helpers ---------------------------------
__device__ __forceinline__ uint32_t u32_of(__nv_bfloat162 v) {
    return *reinterpret_cast<uint32_t*>(&v);
}
__device__ __forceinline__ __nv_bfloat162 bf2_of(uint32_t v) {
    return *reinterpret_cast<__nv_bfloat162*>(&v);
}
__device__ __forceinline__ uint32_t hmul2u(uint32_t a, uint32_t b) {
    __nv_bfloat162 r = __hmul2(bf2_of(a), bf2_of(b));
    return u32_of(r);
}
__device__ __forceinline__ uint32_t bpack(float lo, float hi) {
    __nv_bfloat162 h = __floats2bfloat162_rn(lo, hi);
    return u32_of(h);
}
__device__ __forceinline__ uint32_t smem_u32(const void* p) {
    uint32_t a;
    asm("{ .reg .u64 t; cvta.to.shared.u64 t, %1; cvt.u32.u64 %0, t; }"
        : "=r"(a) : "l"(p));
    return a;
}
__device__ __forceinline__ void mma16816(float* d, const uint32_t* a, const uint32_t* b) {
    asm volatile(
        "mma.sync.aligned.m16n8k16.row.col.f32.bf16.bf16.f32 "
        "{%0,%1,%2,%3}, {%4,%5,%6,%7}, {%8,%9}, {%0,%1,%2,%3};\n"
        : "+f"(d[0]), "+f"(d[1]), "+f"(d[2]), "+f"(d[3])
        : "r"(a[0]), "r"(a[1]), "r"(a[2]), "r"(a[3]), "r"(b[0]), "r"(b[1]));
}

// ----------------------- stage 1: mapping GEMMs (both paths) ----------------
__global__ __launch_bounds__(256) void map_gemm2(const float* __restrict__ Ximg,
                                                 const float* __restrict__ Xtxt,
                                                 const float* __restrict__ Wi,
                                                 const float* __restrict__ bi,
                                                 const float* __restrict__ Wt,
                                                 const float* __restrict__ bt) {
    __shared__ float Xs[32][33];
    __shared__ float Ws[32][33];
    int path = blockIdx.z;
    const float* X = path == 0 ? Ximg : Xtxt;
    const float* W = path == 0 ? Wi : Wt;
    const float* bias = path == 0 ? bi : bt;
    int tid = threadIdx.x;
    int tx = tid & 31, ty = tid >> 5;
    int mt = blockIdx.x, bt_ = blockIdx.y;
    float acc[4] = {0.f, 0.f, 0.f, 0.f};
    for (int d0 = 0; d0 < 512; d0 += 32) {
#pragma unroll
        for (int q = 0; q < 4; ++q) {
            int idx = tid + 256 * q;
            int r = idx >> 5, c = idx & 31;
            Xs[r][c] = X[(bt_ * 32 + r) * 512 + d0 + c];
            Ws[r][c] = W[(mt * 32 + r) * 512 + d0 + c];
        }
        __syncthreads();
#pragma unroll
        for (int kk = 0; kk < 32; ++kk) {
            float w = Ws[tx][kk];
#pragma unroll
            for (int r = 0; r < 4; ++r) acc[r] += Xs[ty + 8 * r][kk] * w;
        }
        __syncthreads();
    }
    float bb = bias[mt * 32 + tx];
#pragma unroll
    for (int r = 0; r < 4; ++r)
        g_pre[path * (B_SZ * M_DIM) + (bt_ * 32 + ty + 8 * r) * 512 + mt * 32 + tx] =
            acc[r] + bb;
}

// ----- stage 2: L2 normalize; img -> transposed bf16x2 table; txt -> bf16 ---
__global__ __launch_bounds__(128) void norm_zero() {
    int bx = blockIdx.x;
    int path = bx >> 8;
    int row = bx & 255;
    int t = threadIdx.x;
    const float* src = g_pre + path * (B_SZ * M_DIM) + row * 512;
    float v[4];
    float ss = 0.f;
#pragma unroll
    for (int q = 0; q < 4; ++q) {
        v[q] = src[t + 128 * q];
        ss += v[q] * v[q];
    }
#pragma unroll
    for (int o = 16; o > 0; o >>= 1) ss += __shfl_xor_sync(0xffffffffu, ss, o);
    __shared__ float sred[4];
    if ((t & 31) == 0) sred[t >> 5] = ss;
    __syncthreads();
    float tot = sred[0] + sred[1] + sred[2] + sred[3];
    float sc = 1.f / fmaxf(sqrtf(tot), 1e-12f);
    if (path == 0) {
#pragma unroll
        for (int q = 0; q < 4; ++q) {
            float val = v[q] * sc;
            g_imgu[(t + 128 * q) * 256 + row] = bpack(val, val);
            g_feats[row * 512 + t + 128 * q] = 0.f;
        }
    } else {
#pragma unroll
        for (int q = 0; q < 4; ++q)
            g_txtb[row * 512 + t + 128 * q] = __float2bfloat16(v[q] * sc);
    }
}

// --------------------- stage 3: the big bilinear GEMM -----------------------
// chunk c in [0,8192): i = c & 511 (fast), jblk = c >> 9 (slow, 16 blocks)
__global__ __launch_bounds__(256, 2) void bilinear_gemm(const float* __restrict__ Wp) {
    extern __shared__ uint32_t smem[];
    float* Bsf = reinterpret_cast<float*>(smem);

    int tid = threadIdx.x;
    int lane = tid & 31, warp = tid >> 5;
    int wm = warp >> 2;                 // 0/1: batch half
    int p = warp & 3;                   // pair id: n range [p*32, p*32+32)
    int tp = wm * 32 + lane;            // 0..63 within pair
    int s = blockIdx.x, nt = blockIdx.y, mt = blockIdx.z;
    int b0 = mt * BM, k0 = nt * BN;

    int kb = (int)(((long)ITERS * s) / SPLITS);
    int ke = (int)(((long)ITERS * (s + 1)) / SPLITS);

    int pb = p * PAIRU;                 // pair ring base (u32)

    // ---- pair-local cp.async: 4 x 16B per thread per chunk (4KB/pair) ----
    // op u: gmem row = p*32 + (tp>>3) + 8u ; smem row = (tp>>3) + 8u
    const float* wp0 = Wp + (size_t)(k0 + p * 32 + (tp >> 3)) * KIJ + (tp & 7) * 4;
    uint32_t smoff0 = (uint32_t)(((tp >> 3) * BSTRP + (tp & 7) * 4) * 4);
    uint32_t bs_addr = smem_u32(smem) + (uint32_t)pb * 4u;

#define BARP() asm volatile("bar.sync %0, 64;" :: "r"(p + 1) : "memory")

#define CPY(chunk, stg)                                                       \
    do {                                                                      \
        if ((chunk) < ke) {                                                   \
            size_t off_ = (size_t)((chunk) & 511) * 512 +                     \
                          (size_t)((chunk) >> 9) * 32;                        \
            uint32_t sa_ = bs_addr + (uint32_t)((stg) * (STGP * 4)) + smoff0; \
            const float* gp_ = wp0 + off_;                                    \
            _Pragma("unroll") for (int u_ = 0; u_ < 4; ++u_) {                \
                asm volatile("cp.async.cg.shared.global [%0], [%1], 16;"      \
                             :: "r"(sa_ + u_ * (8 * BSTRP * 4)),              \
                                "l"(gp_ + (size_t)u_ * 8 * KIJ));             \
            }                                                                 \
        }                                                                     \
        asm volatile("cp.async.commit_group;" ::: "memory");                  \
    } while (0)

    int arow[8];
#pragma unroll
    for (int f = 0; f < 4; ++f) {
        arow[2 * f] = wm * 64 + f * 16 + (lane >> 2);
        arow[2 * f + 1] = arow[2 * f] + 8;
    }

    // ---- prologue ----
    CPY(kb, 0);
    CPY(kb + 1, 1);
    CPY(kb + 2, 2);
    CPY(kb + 3, 3);

    uint32_t im[8];
    {
        int i0 = kb & 511;
#pragma unroll
        for (int h = 0; h < 8; ++h) im[h] = g_imgu[i0 * 256 + b0 + arow[h]];
    }

    float acc[4][4][4];
#pragma unroll
    for (int f = 0; f < 4; ++f)
#pragma unroll
        for (int g = 0; g < 4; ++g)
#pragma unroll
            for (int e = 0; e < 4; ++e) acc[f][g][e] = 0.f;

    int st = 0, stp = 4;
    int c = kb;

    // ---- segmented main loop: txt in registers per j-block ----
#pragma unroll 1
    while (c < ke) {
        int jb = c >> 9;
        int seg_end = (jb + 1) << 9;
        if (seg_end > ke) seg_end = ke;

        // hoist txt operands straight from gmem (u32 = bf16 pair), rare
        uint32_t treg[2][4][4];
        {
            const uint32_t* tb = reinterpret_cast<const uint32_t*>(g_txtb);
#pragma unroll
            for (int k2 = 0; k2 < 2; ++k2) {
                int co = jb * 16 + k2 * 8 + (lane & 3);
#pragma unroll
                for (int f = 0; f < 4; ++f) {
                    const uint32_t* r0 = tb + (size_t)(b0 + arow[2 * f]) * 256;
                    const uint32_t* r1 = tb + (size_t)(b0 + arow[2 * f + 1]) * 256;
                    treg[k2][f][0] = r0[co];
                    treg[k2][f][1] = r1[co];
                    treg[k2][f][2] = r0[co + 4];
                    treg[k2][f][3] = r1[co + 4];
                }
            }
        }

#pragma unroll 2
        for (; c < seg_end; ++c) {
            asm volatile("cp.async.wait_group 3;" ::: "memory");
            BARP();                         // partner's chunk c arrived too

            CPY(c + 4, stp);

            // ---- compute chunk c ----
            {
                const float* bsf = Bsf + pb + st * STGP;
#pragma unroll
                for (int k2 = 0; k2 < 2; ++k2) {
                    uint32_t a[4][4];
#pragma unroll
                    for (int f = 0; f < 4; ++f) {
                        a[f][0] = hmul2u(treg[k2][f][0], im[2 * f]);
                        a[f][1] = hmul2u(treg[k2][f][1], im[2 * f + 1]);
                        a[f][2] = hmul2u(treg[k2][f][2], im[2 * f]);
                        a[f][3] = hmul2u(treg[k2][f][3], im[2 * f + 1]);
                    }
                    uint32_t bb[4][2];
#pragma unroll
                    for (int g = 0; g < 4; ++g) {
                        int nloc = g * 8 + (lane >> 2);
                        const float* pf = bsf + nloc * BSTRP + k2 * 16 + (lane & 3) * 2;
                        float2 v0 = *reinterpret_cast<const float2*>(pf);
                        float2 v1 = *reinterpret_cast<const float2*>(pf + 8);
                        bb[g][0] = bpack(v0.x, v0.y);
                        bb[g][1] = bpack(v1.x, v1.y);
                    }
#pragma unroll
                    for (int f = 0; f < 4; ++f)
#pragma unroll
                        for (int g = 0; g < 4; ++g) mma16816(acc[f][g], a[f], bb[g]);
                }
            }

            {   // img for chunk c+1 (im regs dead after the hmul2s above;
                // L1-resident column, short prefetch distance is enough)
                int i1 = (c + 1) & 511;
#pragma unroll
                for (int h = 0; h < 8; ++h)
                    im[h] = g_imgu[i1 * 256 + b0 + arow[h]];
            }

            st = (st == NSTG - 1) ? 0 : st + 1;
            stp = (stp == NSTG - 1) ? 0 : stp + 1;
        }
    }
    asm volatile("cp.async.wait_group 0;" ::: "memory");

    // ---- split-K epilogue ----
#pragma unroll
    for (int f = 0; f < 4; ++f)
#pragma unroll
        for (int g = 0; g < 4; ++g)
#pragma unroll
            for (int e = 0; e < 4; ++e) {
                int rr = b0 + wm * 64 + f * 16 + (lane >> 2) + ((e >> 1) << 3);
                int cc = k0 + p * 32 + g * 8 + ((lane & 3) << 1) + (e & 1);
                atomicAdd(&g_feats[rr * 512 + cc], acc[f][g][e]);
            }
#undef CPY
#undef BARP
}

// ------------------ stage 4: bias + relu + classifier + sigmoid -------------
__global__ __launch_bounds__(128) void final_k(const float* __restrict__ bp,
                                               const float* __restrict__ Wc,
                                               const float* __restrict__ bc,
                                               float* __restrict__ out) {
    int b = blockIdx.x;
    int t = threadIdx.x;
    float p = 0.f;
    for (int k = t; k < 512; k += 128) {
        float f = g_feats[b * 512 + k] + bp[k];
        f = fmaxf(f, 0.f);
        p += f * Wc[k];
    }
#pragma unroll
    for (int o = 16; o > 0; o >>= 1) p += __shfl_xor_sync(0xffffffffu, p, o);
    __shared__ float sr[4];
    if ((t & 31) == 0) sr[t >> 5] = p;
    __syncthreads();
    if (t == 0) {
        float logit = sr[0] + sr[1] + sr[2] + sr[3] + bc[0];
        out[b] = 1.f / (1.f + expf(-logit));
    }
}

// ------------------------------ launcher ------------------------------------
extern "C" void kernel_launch(void* const* d_in, const int* in_sizes, int n_in,
                              void* d_out, int out_size) {
    const float* img_e = (const float*)d_in[0];
    const float* txt_e = (const float*)d_in[1];
    const float* Wi = (const float*)d_in[2];
    const float* bi = (const float*)d_in[3];
    const float* Wt = (const float*)d_in[4];
    const float* bt = (const float*)d_in[5];
    const float* Wp = (const float*)d_in[6];
    const float* bp = (const float*)d_in[7];
    const float* Wc = (const float*)d_in[8];
    const float* bc = (const float*)d_in[9];
    float* out = (float*)d_out;

    cudaFuncSetAttribute(bilinear_gemm, cudaFuncAttributeMaxDynamicSharedMemorySize,
                         SM_BYTES);

    map_gemm2<<<dim3(16, 8, 2), 256>>>(img_e, txt_e, Wi, bi, Wt, bt);
    norm_zero<<<512, 128>>>();
    bilinear_gemm<<<dim3(SPLITS, 4, 2), 256, SM_BYTES>>>(Wp);
    final_k<<<256, 128>>>(bp, Wc, bc, out);
}

// round 15
// speedup vs baseline: 1.0770x; 1.0770x over previous
#include <cuda_runtime.h>
#include <cuda_bf16.h>
#include <cstdint>

// ---------------------------------------------------------------------------
// CustomBLIP: sigmoid( relu( bilinear(img_n, txt_n; Wp) + bp ) @ Wc^T + bc )
// Core: feats[b,k] = sum_ij (img[b,i]*txt[b,j]) * Wp[k, i*512+j]
//   -> GEMM C[256,512] = A[256,262144] x Wp^T, A generated on the fly.
// R14 = R12 (4 warp-pairs, pair-local 5-stage cp.async rings, 64-thread named
//      barriers, txt regs per j-block, dual img register sets) with the img
//      prefetch LDGs hoisted ABOVE wait_group/BARP so their ~250cyc L2 latency
//      overlaps the barrier wait. R13's shortened-prefetch + unroll2 reverted.
// ---------------------------------------------------------------------------

#define B_SZ   256
#define M_DIM  512
#define KIJ    (512 * 512)          // 262144
#define ITERS  8192                 // chunks of 32 ij
#define BM     128
#define BN     128
#define SPLITS 37                   // 37*4*2 = 296 CTAs = 2/SM

#define NSTG    5                   // stages per pair ring
#define BSTRP   40                  // pair stage row stride in fp32 (32+8 pad)
#define STGP    (32 * BSTRP)        // 1280 u32 per stage
#define PAIRU   (NSTG * STGP)       // 6400 u32 per pair

#define SM_U32_TOT (4 * PAIRU)      // 25600
#define SM_BYTES   (SM_U32_TOT * 4) // 102400 -> 2 CTAs/SM

// -------------------------------- scratch ---------------------------------
__device__ float                        g_pre[2 * B_SZ * M_DIM];
__device__ uint32_t                     g_imgu[M_DIM * B_SZ];  // [i][b] bf16x2
__device__ __align__(16) __nv_bfloat16  g_txtb[B_SZ * M_DIM];  // [b][j]
__device__ float                        g_feats[B_SZ * M_DIM];

// -------------------------------- helpers ---------------------------------
__device__ __forceinline__ uint32_t u32_of(__nv_bfloat162 v) {
    return *reinterpret_cast<uint32_t*>(&v);
}
__device__ __forceinline__ __nv_bfloat162 bf2_of(uint32_t v) {
    return *reinterpret_cast<__nv_bfloat162*>(&v);
}
__device__ __forceinline__ uint32_t hmul2u(uint32_t a, uint32_t b) {
    __nv_bfloat162 r = __hmul2(bf2_of(a), bf2_of(b));
    return u32_of(r);
}
__device__ __forceinline__ uint32_t bpack(float lo, float hi) {
    __nv_bfloat162 h = __floats2bfloat162_rn(lo, hi);
    return u32_of(h);
}
__device__ __forceinline__ uint32_t smem_u32(const void* p) {
    uint32_t a;
    asm("{ .reg .u64 t; cvta.to.shared.u64 t, %1; cvt.u32.u64 %0, t; }"
        : "=r"(a) : "l"(p));
    return a;
}
__device__ __forceinline__ void mma16816(float* d, const uint32_t* a, const uint32_t* b) {
    asm volatile(
        "mma.sync.aligned.m16n8k16.row.col.f32.bf16.bf16.f32 "
        "{%0,%1,%2,%3}, {%4,%5,%6,%7}, {%8,%9}, {%0,%1,%2,%3};\n"
        : "+f"(d[0]), "+f"(d[1]), "+f"(d[2]), "+f"(d[3])
        : "r"(a[0]), "r"(a[1]), "r"(a[2]), "r"(a[3]), "r"(b[0]), "r"(b[1]));
}

// ----------------------- stage 1: mapping GEMMs (both paths) ----------------
__global__ __launch_bounds__(256) void map_gemm2(const float* __restrict__ Ximg,
                                                 const float* __restrict__ Xtxt,
                                                 const float* __restrict__ Wi,
                                                 const float* __restrict__ bi,
                                                 const float* __restrict__ Wt,
                                                 const float* __restrict__ bt) {
    __shared__ float Xs[32][33];
    __shared__ float Ws[32][33];
    int path = blockIdx.z;
    const float* X = path == 0 ? Ximg : Xtxt;
    const float* W = path == 0 ? Wi : Wt;
    const float* bias = path == 0 ? bi : bt;
    int tid = threadIdx.x;
    int tx = tid & 31, ty = tid >> 5;
    int mt = blockIdx.x, bt_ = blockIdx.y;
    float acc[4] = {0.f, 0.f, 0.f, 0.f};
    for (int d0 = 0; d0 < 512; d0 += 32) {
#pragma unroll
        for (int q = 0; q < 4; ++q) {
            int idx = tid + 256 * q;
            int r = idx >> 5, c = idx & 31;
            Xs[r][c] = X[(bt_ * 32 + r) * 512 + d0 + c];
            Ws[r][c] = W[(mt * 32 + r) * 512 + d0 + c];
        }
        __syncthreads();
#pragma unroll
        for (int kk = 0; kk < 32; ++kk) {
            float w = Ws[tx][kk];
#pragma unroll
            for (int r = 0; r < 4; ++r) acc[r] += Xs[ty + 8 * r][kk] * w;
        }
        __syncthreads();
    }
    float bb = bias[mt * 32 + tx];
#pragma unroll
    for (int r = 0; r < 4; ++r)
        g_pre[path * (B_SZ * M_DIM) + (bt_ * 32 + ty + 8 * r) * 512 + mt * 32 + tx] =
            acc[r] + bb;
}

// ----- stage 2: L2 normalize; img -> transposed bf16x2 table; txt -> bf16 ---
__global__ __launch_bounds__(128) void norm_zero() {
    int bx = blockIdx.x;
    int path = bx >> 8;
    int row = bx & 255;
    int t = threadIdx.x;
    const float* src = g_pre + path * (B_SZ * M_DIM) + row * 512;
    float v[4];
    float ss = 0.f;
#pragma unroll
    for (int q = 0; q < 4; ++q) {
        v[q] = src[t + 128 * q];
        ss += v[q] * v[q];
    }
#pragma unroll
    for (int o = 16; o > 0; o >>= 1) ss += __shfl_xor_sync(0xffffffffu, ss, o);
    __shared__ float sred[4];
    if ((t & 31) == 0) sred[t >> 5] = ss;
    __syncthreads();
    float tot = sred[0] + sred[1] + sred[2] + sred[3];
    float sc = 1.f / fmaxf(sqrtf(tot), 1e-12f);
    if (path == 0) {
#pragma unroll
        for (int q = 0; q < 4; ++q) {
            float val = v[q] * sc;
            g_imgu[(t + 128 * q) * 256 + row] = bpack(val, val);
            g_feats[row * 512 + t + 128 * q] = 0.f;
        }
    } else {
#pragma unroll
        for (int q = 0; q < 4; ++q)
            g_txtb[row * 512 + t + 128 * q] = __float2bfloat16(v[q] * sc);
    }
}

// --------------------- stage 3: the big bilinear GEMM -----------------------
// chunk c in [0,8192): i = c & 511 (fast), jblk = c >> 9 (slow, 16 blocks)
__global__ __launch_bounds__(256, 2) void bilinear_gemm(const float* __restrict__ Wp) {
    extern __shared__ uint32_t smem[];
    float* Bsf = reinterpret_cast<float*>(smem);

    int tid = threadIdx.x;
    int lane = tid & 31, warp = tid >> 5;
    int wm = warp >> 2;                 // 0/1: batch half
    int p = warp & 3;                   // pair id: n range [p*32, p*32+32)
    int tp = wm * 32 + lane;            // 0..63 within pair
    int s = blockIdx.x, nt = blockIdx.y, mt = blockIdx.z;
    int b0 = mt * BM, k0 = nt * BN;

    int kb = (int)(((long)ITERS * s) / SPLITS);
    int ke = (int)(((long)ITERS * (s + 1)) / SPLITS);

    int pb = p * PAIRU;                 // pair ring base (u32)

    // ---- pair-local cp.async: 4 x 16B per thread per chunk (4KB/pair) ----
    // op u: gmem row = p*32 + (tp>>3) + 8u ; smem row = (tp>>3) + 8u
    const float* wp0 = Wp + (size_t)(k0 + p * 32 + (tp >> 3)) * KIJ + (tp & 7) * 4;
    uint32_t smoff0 = (uint32_t)(((tp >> 3) * BSTRP + (tp & 7) * 4) * 4);
    uint32_t bs_addr = smem_u32(smem) + (uint32_t)pb * 4u;

#define BARP() asm volatile("bar.sync %0, 64;" :: "r"(p + 1) : "memory")

#define CPY(chunk, stg)                                                       \
    do {                                                                      \
        if ((chunk) < ke) {                                                   \
            size_t off_ = (size_t)((chunk) & 511) * 512 +                     \
                          (size_t)((chunk) >> 9) * 32;                        \
            uint32_t sa_ = bs_addr + (uint32_t)((stg) * (STGP * 4)) + smoff0; \
            const float* gp_ = wp0 + off_;                                    \
            _Pragma("unroll") for (int u_ = 0; u_ < 4; ++u_) {                \
                asm volatile("cp.async.cg.shared.global [%0], [%1], 16;"      \
                             :: "r"(sa_ + u_ * (8 * BSTRP * 4)),              \
                                "l"(gp_ + (size_t)u_ * 8 * KIJ));             \
            }                                                                 \
        }                                                                     \
        asm volatile("cp.async.commit_group;" ::: "memory");                  \
    } while (0)

    int arow[8];
#pragma unroll
    for (int f = 0; f < 4; ++f) {
        arow[2 * f] = wm * 64 + f * 16 + (lane >> 2);
        arow[2 * f + 1] = arow[2 * f] + 8;
    }

    // ---- prologue ----
    CPY(kb, 0);
    CPY(kb + 1, 1);
    CPY(kb + 2, 2);
    CPY(kb + 3, 3);

    uint32_t im_a[8], im_b[8];
    {
        int i0 = kb & 511;
#pragma unroll
        for (int h = 0; h < 8; ++h) im_a[h] = g_imgu[i0 * 256 + b0 + arow[h]];
    }

    float acc[4][4][4];
#pragma unroll
    for (int f = 0; f < 4; ++f)
#pragma unroll
        for (int g = 0; g < 4; ++g)
#pragma unroll
            for (int e = 0; e < 4; ++e) acc[f][g][e] = 0.f;

    int st = 0, stp = 4;
    int c = kb;

    // ---- segmented main loop: txt in registers per j-block ----
#pragma unroll 1
    while (c < ke) {
        int jb = c >> 9;
        int seg_end = (jb + 1) << 9;
        if (seg_end > ke) seg_end = ke;

        // hoist txt operands straight from gmem (u32 = bf16 pair), rare
        uint32_t treg[2][4][4];
        {
            const uint32_t* tb = reinterpret_cast<const uint32_t*>(g_txtb);
#pragma unroll
            for (int k2 = 0; k2 < 2; ++k2) {
                int co = jb * 16 + k2 * 8 + (lane & 3);
#pragma unroll
                for (int f = 0; f < 4; ++f) {
                    const uint32_t* r0 = tb + (size_t)(b0 + arow[2 * f]) * 256;
                    const uint32_t* r1 = tb + (size_t)(b0 + arow[2 * f + 1]) * 256;
                    treg[k2][f][0] = r0[co];
                    treg[k2][f][1] = r1[co];
                    treg[k2][f][2] = r0[co + 4];
                    treg[k2][f][3] = r1[co + 4];
                }
            }
        }

#pragma unroll 1
        for (; c < seg_end; ++c) {
            {   // img prefetch for c+1 issued BEFORE the barrier: its L2
                // latency overlaps the wait below (im_b unused until c+1)
                int i1 = (c + 1) & 511;
#pragma unroll
                for (int h = 0; h < 8; ++h)
                    im_b[h] = g_imgu[i1 * 256 + b0 + arow[h]];
            }

            asm volatile("cp.async.wait_group 3;" ::: "memory");
            BARP();                         // partner's chunk c arrived too

            CPY(c + 4, stp);

            // ---- compute chunk c ----
            {
                const float* bsf = Bsf + pb + st * STGP;
#pragma unroll
                for (int k2 = 0; k2 < 2; ++k2) {
                    uint32_t a[4][4];
#pragma unroll
                    for (int f = 0; f < 4; ++f) {
                        a[f][0] = hmul2u(treg[k2][f][0], im_a[2 * f]);
                        a[f][1] = hmul2u(treg[k2][f][1], im_a[2 * f + 1]);
                        a[f][2] = hmul2u(treg[k2][f][2], im_a[2 * f]);
                        a[f][3] = hmul2u(treg[k2][f][3], im_a[2 * f + 1]);
                    }
                    uint32_t bb[4][2];
#pragma unroll
                    for (int g = 0; g < 4; ++g) {
                        int nloc = g * 8 + (lane >> 2);
                        const float* pf = bsf + nloc * BSTRP + k2 * 16 + (lane & 3) * 2;
                        float2 v0 = *reinterpret_cast<const float2*>(pf);
                        float2 v1 = *reinterpret_cast<const float2*>(pf + 8);
                        bb[g][0] = bpack(v0.x, v0.y);
                        bb[g][1] = bpack(v1.x, v1.y);
                    }
#pragma unroll
                    for (int f = 0; f < 4; ++f)
#pragma unroll
                        for (int g = 0; g < 4; ++g) mma16816(acc[f][g], a[f], bb[g]);
                }
            }

#pragma unroll
            for (int h = 0; h < 8; ++h) im_a[h] = im_b[h];

            st = (st == NSTG - 1) ? 0 : st + 1;
            stp = (stp == NSTG - 1) ? 0 : stp + 1;
        }
    }
    asm volatile("cp.async.wait_group 0;" ::: "memory");

    // ---- split-K epilogue ----
#pragma unroll
    for (int f = 0; f < 4; ++f)
#pragma unroll
        for (int g = 0; g < 4; ++g)
#pragma unroll
            for (int e = 0; e < 4; ++e) {
                int rr = b0 + wm * 64 + f * 16 + (lane >> 2) + ((e >> 1) << 3);
                int cc = k0 + p * 32 + g * 8 + ((lane & 3) << 1) + (e & 1);
                atomicAdd(&g_feats[rr * 512 + cc], acc[f][g][e]);
            }
#undef CPY
#undef BARP
}

// ------------------ stage 4: bias + relu + classifier + sigmoid -------------
__global__ __launch_bounds__(128) void final_k(const float* __restrict__ bp,
                                               const float* __restrict__ Wc,
                                               const float* __restrict__ bc,
                                               float* __restrict__ out) {
    int b = blockIdx.x;
    int t = threadIdx.x;
    float p = 0.f;
    for (int k = t; k < 512; k += 128) {
        float f = g_feats[b * 512 + k] + bp[k];
        f = fmaxf(f, 0.f);
        p += f * Wc[k];
    }
#pragma unroll
    for (int o = 16; o > 0; o >>= 1) p += __shfl_xor_sync(0xffffffffu, p, o);
    __shared__ float sr[4];
    if ((t & 31) == 0) sr[t >> 5] = p;
    __syncthreads();
    if (t == 0) {
        float logit = sr[0] + sr[1] + sr[2] + sr[3] + bc[0];
        out[b] = 1.f / (1.f + expf(-logit));
    }
}

// ------------------------------ launcher ------------------------------------
extern "C" void kernel_launch(void* const* d_in, const int* in_sizes, int n_in,
                              void* d_out, int out_size) {
    const float* img_e = (const float*)d_in[0];
    const float* txt_e = (const float*)d_in[1];
    const float* Wi = (const float*)d_in[2];
    const float* bi = (const float*)d_in[3];
    const float* Wt = (const float*)d_in[4];
    const float* bt = (const float*)d_in[5];
    const float* Wp = (const float*)d_in[6];
    const float* bp = (const float*)d_in[7];
    const float* Wc = (const float*)d_in[8];
    const float* bc = (const float*)d_in[9];
    float* out = (float*)d_out;

    cudaFuncSetAttribute(bilinear_gemm, cudaFuncAttributeMaxDynamicSharedMemorySize,
                         SM_BYTES);

    map_gemm2<<<dim3(16, 8, 2), 256>>>(img_e, txt_e, Wi, bi, Wt, bt);
    norm_zero<<<512, 128>>>();
    bilinear_gemm<<<dim3(SPLITS, 4, 2), 256, SM_BYTES>>>(Wp);
    final_k<<<256, 128>>>(bp, Wc, bc, out);
}

// round 16
// speedup vs baseline: 1.2338x; 1.1456x over previous
#include <cuda_runtime.h>
#include <cuda_bf16.h>
#include <cstdint>

// ---------------------------------------------------------------------------
// CustomBLIP: sigmoid( relu( bilinear(img_n, txt_n; Wp) + bp ) @ Wc^T + bc )
// Core: feats[b,k] = sum_ij (img[b,i]*txt[b,j]) * Wp[k, i*512+j]
//   -> GEMM C[256,512] = A[256,262144] x Wp^T, A generated on the fly.
// R15 = R12 main kernel restored byte-for-byte (proven 250us; R13/R14
//      scheduling tweaks both regressed and are reverted). Prep trimmed:
//      norm_zero now does both paths in one block (256 blocks, not 512).
// ---------------------------------------------------------------------------

#define B_SZ   256
#define M_DIM  512
#define KIJ    (512 * 512)          // 262144
#define ITERS  8192                 // chunks of 32 ij
#define BM     128
#define BN     128
#define SPLITS 37                   // 37*4*2 = 296 CTAs = 2/SM

#define NSTG    5                   // stages per pair ring
#define BSTRP   40                  // pair stage row stride in fp32 (32+8 pad)
#define STGP    (32 * BSTRP)        // 1280 u32 per stage
#define PAIRU   (NSTG * STGP)       // 6400 u32 per pair

#define SM_U32_TOT (4 * PAIRU)      // 25600
#define SM_BYTES   (SM_U32_TOT * 4) // 102400 -> 2 CTAs/SM

// -------------------------------- scratch ---------------------------------
__device__ float                        g_pre[2 * B_SZ * M_DIM];
__device__ uint32_t                     g_imgu[M_DIM * B_SZ];  // [i][b] bf16x2
__device__ __align__(16) __nv_bfloat16  g_txtb[B_SZ * M_DIM];  // [b][j]
__device__ float                        g_feats[B_SZ * M_DIM];

// -------------------------------- helpers ---------------------------------
__device__ __forceinline__ uint32_t u32_of(__nv_bfloat162 v) {
    return *reinterpret_cast<uint32_t*>(&v);
}
__device__ __forceinline__ __nv_bfloat162 bf2_of(uint32_t v) {
    return *reinterpret_cast<__nv_bfloat162*>(&v);
}
__device__ __forceinline__ uint32_t hmul2u(uint32_t a, uint32_t b) {
    __nv_bfloat162 r = __hmul2(bf2_of(a), bf2_of(b));
    return u32_of(r);
}
__device__ __forceinline__ uint32_t bpack(float lo, float hi) {
    __nv_bfloat162 h = __floats2bfloat162_rn(lo, hi);
    return u32_of(h);
}
__device__ __forceinline__ uint32_t smem_u32(const void* p) {
    uint32_t a;
    asm("{ .reg .u64 t; cvta.to.shared.u64 t, %1; cvt.u32.u64 %0, t; }"
        : "=r"(a) : "l"(p));
    return a;
}
__device__ __forceinline__ void mma16816(float* d, const uint32_t* a, const uint32_t* b) {
    asm volatile(
        "mma.sync.aligned.m16n8k16.row.col.f32.bf16.bf16.f32 "
        "{%0,%1,%2,%3}, {%4,%5,%6,%7}, {%8,%9}, {%0,%1,%2,%3};\n"
        : "+f"(d[0]), "+f"(d[1]), "+f"(d[2]), "+f"(d[3])
        : "r"(a[0]), "r"(a[1]), "r"(a[2]), "r"(a[3]), "r"(b[0]), "r"(b[1]));
}

// ----------------------- stage 1: mapping GEMMs (both paths) ----------------
__global__ __launch_bounds__(256) void map_gemm2(const float* __restrict__ Ximg,
                                                 const float* __restrict__ Xtxt,
                                                 const float* __restrict__ Wi,
                                                 const float* __restrict__ bi,
                                                 const float* __restrict__ Wt,
                                                 const float* __restrict__ bt) {
    __shared__ float Xs[32][33];
    __shared__ float Ws[32][33];
    int path = blockIdx.z;
    const float* X = path == 0 ? Ximg : Xtxt;
    const float* W = path == 0 ? Wi : Wt;
    const float* bias = path == 0 ? bi : bt;
    int tid = threadIdx.x;
    int tx = tid & 31, ty = tid >> 5;
    int mt = blockIdx.x, bt_ = blockIdx.y;
    float acc[4] = {0.f, 0.f, 0.f, 0.f};
    for (int d0 = 0; d0 < 512; d0 += 32) {
#pragma unroll
        for (int q = 0; q < 4; ++q) {
            int idx = tid + 256 * q;
            int r = idx >> 5, c = idx & 31;
            Xs[r][c] = X[(bt_ * 32 + r) * 512 + d0 + c];
            Ws[r][c] = W[(mt * 32 + r) * 512 + d0 + c];
        }
        __syncthreads();
#pragma unroll
        for (int kk = 0; kk < 32; ++kk) {
            float w = Ws[tx][kk];
#pragma unroll
            for (int r = 0; r < 4; ++r) acc[r] += Xs[ty + 8 * r][kk] * w;
        }
        __syncthreads();
    }
    float bb = bias[mt * 32 + tx];
#pragma unroll
    for (int r = 0; r < 4; ++r)
        g_pre[path * (B_SZ * M_DIM) + (bt_ * 32 + ty + 8 * r) * 512 + mt * 32 + tx] =
            acc[r] + bb;
}

// ----- stage 2: L2 normalize BOTH paths per block; img -> bf16x2 table ------
__global__ __launch_bounds__(256) void norm_zero2() {
    int row = blockIdx.x;              // batch row 0..255
    int t = threadIdx.x;
    int path = t >> 7;                 // 0: img (threads 0-127), 1: txt
    int th = t & 127;
    const float* src = g_pre + path * (B_SZ * M_DIM) + row * 512;
    float v[4];
    float ss = 0.f;
#pragma unroll
    for (int q = 0; q < 4; ++q) {
        v[q] = src[th + 128 * q];
        ss += v[q] * v[q];
    }
#pragma unroll
    for (int o = 16; o > 0; o >>= 1) ss += __shfl_xor_sync(0xffffffffu, ss, o);
    __shared__ float sred[8];          // warps 0-3: path0, 4-7: path1
    if ((t & 31) == 0) sred[t >> 5] = ss;
    __syncthreads();
    int base = path * 4;
    float tot = sred[base] + sred[base + 1] + sred[base + 2] + sred[base + 3];
    float sc = 1.f / fmaxf(sqrtf(tot), 1e-12f);
    if (path == 0) {
#pragma unroll
        for (int q = 0; q < 4; ++q) {
            float val = v[q] * sc;
            g_imgu[(th + 128 * q) * 256 + row] = bpack(val, val);
            g_feats[row * 512 + th + 128 * q] = 0.f;
        }
    } else {
#pragma unroll
        for (int q = 0; q < 4; ++q)
            g_txtb[row * 512 + th + 128 * q] = __float2bfloat16(v[q] * sc);
    }
}

// --------------------- stage 3: the big bilinear GEMM -----------------------
// chunk c in [0,8192): i = c & 511 (fast), jblk = c >> 9 (slow, 16 blocks)
__global__ __launch_bounds__(256, 2) void bilinear_gemm(const float* __restrict__ Wp) {
    extern __shared__ uint32_t smem[];
    float* Bsf = reinterpret_cast<float*>(smem);

    int tid = threadIdx.x;
    int lane = tid & 31, warp = tid >> 5;
    int wm = warp >> 2;                 // 0/1: batch half
    int p = warp & 3;                   // pair id: n range [p*32, p*32+32)
    int tp = wm * 32 + lane;            // 0..63 within pair
    int s = blockIdx.x, nt = blockIdx.y, mt = blockIdx.z;
    int b0 = mt * BM, k0 = nt * BN;

    int kb = (int)(((long)ITERS * s) / SPLITS);
    int ke = (int)(((long)ITERS * (s + 1)) / SPLITS);

    int pb = p * PAIRU;                 // pair ring base (u32)

    // ---- pair-local cp.async: 4 x 16B per thread per chunk (4KB/pair) ----
    // op u: gmem row = p*32 + (tp>>3) + 8u ; smem row = (tp>>3) + 8u
    const float* wp0 = Wp + (size_t)(k0 + p * 32 + (tp >> 3)) * KIJ + (tp & 7) * 4;
    uint32_t smoff0 = (uint32_t)(((tp >> 3) * BSTRP + (tp & 7) * 4) * 4);
    uint32_t bs_addr = smem_u32(smem) + (uint32_t)pb * 4u;

#define BARP() asm volatile("bar.sync %0, 64;" :: "r"(p + 1) : "memory")

#define CPY(chunk, stg)                                                       \
    do {                                                                      \
        if ((chunk) < ke) {                                                   \
            size_t off_ = (size_t)((chunk) & 511) * 512 +                     \
                          (size_t)((chunk) >> 9) * 32;                        \
            uint32_t sa_ = bs_addr + (uint32_t)((stg) * (STGP * 4)) + smoff0; \
            const float* gp_ = wp0 + off_;                                    \
            _Pragma("unroll") for (int u_ = 0; u_ < 4; ++u_) {                \
                asm volatile("cp.async.cg.shared.global [%0], [%1], 16;"      \
                             :: "r"(sa_ + u_ * (8 * BSTRP * 4)),              \
                                "l"(gp_ + (size_t)u_ * 8 * KIJ));             \
            }                                                                 \
        }                                                                     \
        asm volatile("cp.async.commit_group;" ::: "memory");                  \
    } while (0)

    int arow[8];
#pragma unroll
    for (int f = 0; f < 4; ++f) {
        arow[2 * f] = wm * 64 + f * 16 + (lane >> 2);
        arow[2 * f + 1] = arow[2 * f] + 8;
    }

    // ---- prologue ----
    CPY(kb, 0);
    CPY(kb + 1, 1);
    CPY(kb + 2, 2);
    CPY(kb + 3, 3);

    uint32_t im_a[8], im_b[8];
    {
        int i0 = kb & 511;
#pragma unroll
        for (int h = 0; h < 8; ++h) im_a[h] = g_imgu[i0 * 256 + b0 + arow[h]];
    }

    float acc[4][4][4];
#pragma unroll
    for (int f = 0; f < 4; ++f)
#pragma unroll
        for (int g = 0; g < 4; ++g)
#pragma unroll
            for (int e = 0; e < 4; ++e) acc[f][g][e] = 0.f;

    int st = 0, stp = 4;
    int c = kb;

    // ---- segmented main loop: txt in registers per j-block ----
#pragma unroll 1
    while (c < ke) {
        int jb = c >> 9;
        int seg_end = (jb + 1) << 9;
        if (seg_end > ke) seg_end = ke;

        // hoist txt operands straight from gmem (u32 = bf16 pair), rare
        uint32_t treg[2][4][4];
        {
            const uint32_t* tb = reinterpret_cast<const uint32_t*>(g_txtb);
#pragma unroll
            for (int k2 = 0; k2 < 2; ++k2) {
                int co = jb * 16 + k2 * 8 + (lane & 3);
#pragma unroll
                for (int f = 0; f < 4; ++f) {
                    const uint32_t* r0 = tb + (size_t)(b0 + arow[2 * f]) * 256;
                    const uint32_t* r1 = tb + (size_t)(b0 + arow[2 * f + 1]) * 256;
                    treg[k2][f][0] = r0[co];
                    treg[k2][f][1] = r1[co];
                    treg[k2][f][2] = r0[co + 4];
                    treg[k2][f][3] = r1[co + 4];
                }
            }
        }

#pragma unroll 1
        for (; c < seg_end; ++c) {
            asm volatile("cp.async.wait_group 3;" ::: "memory");
            BARP();                         // partner's chunk c arrived too

            CPY(c + 4, stp);

            {   // img prefetch for c+1 (address always valid)
                int i1 = (c + 1) & 511;
#pragma unroll
                for (int h = 0; h < 8; ++h)
                    im_b[h] = g_imgu[i1 * 256 + b0 + arow[h]];
            }

            // ---- compute chunk c ----
            {
                const float* bsf = Bsf + pb + st * STGP;
#pragma unroll
                for (int k2 = 0; k2 < 2; ++k2) {
                    uint32_t a[4][4];
#pragma unroll
                    for (int f = 0; f < 4; ++f) {
                        a[f][0] = hmul2u(treg[k2][f][0], im_a[2 * f]);
                        a[f][1] = hmul2u(treg[k2][f][1], im_a[2 * f + 1]);
                        a[f][2] = hmul2u(treg[k2][f][2], im_a[2 * f]);
                        a[f][3] = hmul2u(treg[k2][f][3], im_a[2 * f + 1]);
                    }
                    uint32_t bb[4][2];
#pragma unroll
                    for (int g = 0; g < 4; ++g) {
                        int nloc = g * 8 + (lane >> 2);
                        const float* pf = bsf + nloc * BSTRP + k2 * 16 + (lane & 3) * 2;
                        float2 v0 = *reinterpret_cast<const float2*>(pf);
                        float2 v1 = *reinterpret_cast<const float2*>(pf + 8);
                        bb[g][0] = bpack(v0.x, v0.y);
                        bb[g][1] = bpack(v1.x, v1.y);
                    }
#pragma unroll
                    for (int f = 0; f < 4; ++f)
#pragma unroll
                        for (int g = 0; g < 4; ++g) mma16816(acc[f][g], a[f], bb[g]);
                }
            }

#pragma unroll
            for (int h = 0; h < 8; ++h) im_a[h] = im_b[h];

            st = (st == NSTG - 1) ? 0 : st + 1;
            stp = (stp == NSTG - 1) ? 0 : stp + 1;
        }
    }
    asm volatile("cp.async.wait_group 0;" ::: "memory");

    // ---- split-K epilogue ----
#pragma unroll
    for (int f = 0; f < 4; ++f)
#pragma unroll
        for (int g = 0; g < 4; ++g)
#pragma unroll
            for (int e = 0; e < 4; ++e) {
                int rr = b0 + wm * 64 + f * 16 + (lane >> 2) + ((e >> 1) << 3);
                int cc = k0 + p * 32 + g * 8 + ((lane & 3) << 1) + (e & 1);
                atomicAdd(&g_feats[rr * 512 + cc], acc[f][g][e]);
            }
#undef CPY
#undef BARP
}

// ------------------ stage 4: bias + relu + classifier + sigmoid -------------
__global__ __launch_bounds__(128) void final_k(const float* __restrict__ bp,
                                               const float* __restrict__ Wc,
                                               const float* __restrict__ bc,
                                               float* __restrict__ out) {
    int b = blockIdx.x;
    int t = threadIdx.x;
    float p = 0.f;
    for (int k = t; k < 512; k += 128) {
        float f = g_feats[b * 512 + k] + bp[k];
        f = fmaxf(f, 0.f);
        p += f * Wc[k];
    }
#pragma unroll
    for (int o = 16; o > 0; o >>= 1) p += __shfl_xor_sync(0xffffffffu, p, o);
    __shared__ float sr[4];
    if ((t & 31) == 0) sr[t >> 5] = p;
    __syncthreads();
    if (t == 0) {
        float logit = sr[0] + sr[1] + sr[2] + sr[3] + bc[0];
        out[b] = 1.f / (1.f + expf(-logit));
    }
}

// ------------------------------ launcher ------------------------------------
extern "C" void kernel_launch(void* const* d_in, const int* in_sizes, int n_in,
                              void* d_out, int out_size) {
    const float* img_e = (const float*)d_in[0];
    const float* txt_e = (const float*)d_in[1];
    const float* Wi = (const float*)d_in[2];
    const float* bi = (const float*)d_in[3];
    const float* Wt = (const float*)d_in[4];
    const float* bt = (const float*)d_in[5];
    const float* Wp = (const float*)d_in[6];
    const float* bp = (const float*)d_in[7];
    const float* Wc = (const float*)d_in[8];
    const float* bc = (const float*)d_in[9];
    float* out = (float*)d_out;

    cudaFuncSetAttribute(bilinear_gemm, cudaFuncAttributeMaxDynamicSharedMemorySize,
                         SM_BYTES);

    map_gemm2<<<dim3(16, 8, 2), 256>>>(img_e, txt_e, Wi, bi, Wt, bt);
    norm_zero2<<<256, 256>>>();
    bilinear_gemm<<<dim3(SPLITS, 4, 2), 256, SM_BYTES>>>(Wp);
    final_k<<<256, 128>>>(bp, Wc, bc, out);
}

// round 17
// speedup vs baseline: 1.2438x; 1.0081x over previous
#include <cuda_runtime.h>
#include <cuda_bf16.h>
#include <cstdint>

// ---------------------------------------------------------------------------
// CustomBLIP: sigmoid( relu( bilinear(img_n, txt_n; Wp) + bp ) @ Wc^T + bc )
// Core: feats[b,k] = sum_ij (img[b,i]*txt[b,j]) * Wp[k, i*512+j]
//   -> GEMM C[256,512] = A[256,262144] x Wp^T, A generated on the fly.
// R16 = R15 with bilinear_gemm UNTOUCHED (proven 250us equilibrium; every
//      main-loop perturbation in R13-R15 regressed). Prep/final vectorized:
//      final_k uses float4 loads (3x LDG.128/thread), norm uses float4 I/O.
// ---------------------------------------------------------------------------

#define B_SZ   256
#define M_DIM  512
#define KIJ    (512 * 512)          // 262144
#define ITERS  8192                 // chunks of 32 ij
#define BM     128
#define BN     128
#define SPLITS 37                   // 37*4*2 = 296 CTAs = 2/SM

#define NSTG    5                   // stages per pair ring
#define BSTRP   40                  // pair stage row stride in fp32 (32+8 pad)
#define STGP    (32 * BSTRP)        // 1280 u32 per stage
#define PAIRU   (NSTG * STGP)       // 6400 u32 per pair

#define SM_U32_TOT (4 * PAIRU)      // 25600
#define SM_BYTES   (SM_U32_TOT * 4) // 102400 -> 2 CTAs/SM

// -------------------------------- scratch ---------------------------------
__device__ float                        g_pre[2 * B_SZ * M_DIM];
__device__ uint32_t                     g_imgu[M_DIM * B_SZ];  // [i][b] bf16x2
__device__ __align__(16) __nv_bfloat16  g_txtb[B_SZ * M_DIM];  // [b][j]
__device__ __align__(16) float          g_feats[B_SZ * M_DIM];

// -------------------------------- helpers ---------------------------------
__device__ __forceinline__ uint32_t u32_of(__nv_bfloat162 v) {
    return *reinterpret_cast<uint32_t*>(&v);
}
__device__ __forceinline__ __nv_bfloat162 bf2_of(uint32_t v) {
    return *reinterpret_cast<__nv_bfloat162*>(&v);
}
__device__ __forceinline__ uint32_t hmul2u(uint32_t a, uint32_t b) {
    __nv_bfloat162 r = __hmul2(bf2_of(a), bf2_of(b));
    return u32_of(r);
}
__device__ __forceinline__ uint32_t bpack(float lo, float hi) {
    __nv_bfloat162 h = __floats2bfloat162_rn(lo, hi);
    return u32_of(h);
}
__device__ __forceinline__ uint32_t smem_u32(const void* p) {
    uint32_t a;
    asm("{ .reg .u64 t; cvta.to.shared.u64 t, %1; cvt.u32.u64 %0, t; }"
        : "=r"(a) : "l"(p));
    return a;
}
__device__ __forceinline__ void mma16816(float* d, const uint32_t* a, const uint32_t* b) {
    asm volatile(
        "mma.sync.aligned.m16n8k16.row.col.f32.bf16.bf16.f32 "
        "{%0,%1,%2,%3}, {%4,%5,%6,%7}, {%8,%9}, {%0,%1,%2,%3};\n"
        : "+f"(d[0]), "+f"(d[1]), "+f"(d[2]), "+f"(d[3])
        : "r"(a[0]), "r"(a[1]), "r"(a[2]), "r"(a[3]), "r"(b[0]), "r"(b[1]));
}

// ----------------------- stage 1: mapping GEMMs (both paths) ----------------
__global__ __launch_bounds__(256) void map_gemm2(const float* __restrict__ Ximg,
                                                 const float* __restrict__ Xtxt,
                                                 const float* __restrict__ Wi,
                                                 const float* __restrict__ bi,
                                                 const float* __restrict__ Wt,
                                                 const float* __restrict__ bt) {
    __shared__ float Xs[32][33];
    __shared__ float Ws[32][33];
    int path = blockIdx.z;
    const float* X = path == 0 ? Ximg : Xtxt;
    const float* W = path == 0 ? Wi : Wt;
    const float* bias = path == 0 ? bi : bt;
    int tid = threadIdx.x;
    int tx = tid & 31, ty = tid >> 5;
    int mt = blockIdx.x, bt_ = blockIdx.y;
    float acc[4] = {0.f, 0.f, 0.f, 0.f};
    for (int d0 = 0; d0 < 512; d0 += 32) {
#pragma unroll
        for (int q = 0; q < 4; ++q) {
            int idx = tid + 256 * q;
            int r = idx >> 5, c = idx & 31;
            Xs[r][c] = X[(bt_ * 32 + r) * 512 + d0 + c];
            Ws[r][c] = W[(mt * 32 + r) * 512 + d0 + c];
        }
        __syncthreads();
#pragma unroll
        for (int kk = 0; kk < 32; ++kk) {
            float w = Ws[tx][kk];
#pragma unroll
            for (int r = 0; r < 4; ++r) acc[r] += Xs[ty + 8 * r][kk] * w;
        }
        __syncthreads();
    }
    float bb = bias[mt * 32 + tx];
#pragma unroll
    for (int r = 0; r < 4; ++r)
        g_pre[path * (B_SZ * M_DIM) + (bt_ * 32 + ty + 8 * r) * 512 + mt * 32 + tx] =
            acc[r] + bb;
}

// ----- stage 2: L2 normalize BOTH paths per block; float4 I/O ---------------
__global__ __launch_bounds__(256) void norm_zero2() {
    int row = blockIdx.x;              // batch row 0..255
    int t = threadIdx.x;
    int path = t >> 7;                 // 0: img (threads 0-127), 1: txt
    int th = t & 127;
    const float4* src = reinterpret_cast<const float4*>(
        g_pre + path * (B_SZ * M_DIM) + row * 512);
    float4 v = src[th];                // elements 4*th .. 4*th+3
    float ss = v.x * v.x + v.y * v.y + v.z * v.z + v.w * v.w;
#pragma unroll
    for (int o = 16; o > 0; o >>= 1) ss += __shfl_xor_sync(0xffffffffu, ss, o);
    __shared__ float sred[8];          // warps 0-3: path0, 4-7: path1
    if ((t & 31) == 0) sred[t >> 5] = ss;
    __syncthreads();
    int base = path * 4;
    float tot = sred[base] + sred[base + 1] + sred[base + 2] + sred[base + 3];
    float sc = 1.f / fmaxf(sqrtf(tot), 1e-12f);
    v.x *= sc; v.y *= sc; v.z *= sc; v.w *= sc;
    if (path == 0) {
        int i0 = th * 4;
        g_imgu[(i0 + 0) * 256 + row] = bpack(v.x, v.x);
        g_imgu[(i0 + 1) * 256 + row] = bpack(v.y, v.y);
        g_imgu[(i0 + 2) * 256 + row] = bpack(v.z, v.z);
        g_imgu[(i0 + 3) * 256 + row] = bpack(v.w, v.w);
        float4 z = {0.f, 0.f, 0.f, 0.f};
        reinterpret_cast<float4*>(g_feats + row * 512)[th] = z;
    } else {
        uint2 pk;
        pk.x = bpack(v.x, v.y);
        pk.y = bpack(v.z, v.w);
        reinterpret_cast<uint2*>(g_txtb + row * 512)[th] = pk;
    }
}

// --------------------- stage 3: the big bilinear GEMM -----------------------
// chunk c in [0,8192): i = c & 511 (fast), jblk = c >> 9 (slow, 16 blocks)
__global__ __launch_bounds__(256, 2) void bilinear_gemm(const float* __restrict__ Wp) {
    extern __shared__ uint32_t smem[];
    float* Bsf = reinterpret_cast<float*>(smem);

    int tid = threadIdx.x;
    int lane = tid & 31, warp = tid >> 5;
    int wm = warp >> 2;                 // 0/1: batch half
    int p = warp & 3;                   // pair id: n range [p*32, p*32+32)
    int tp = wm * 32 + lane;            // 0..63 within pair
    int s = blockIdx.x, nt = blockIdx.y, mt = blockIdx.z;
    int b0 = mt * BM, k0 = nt * BN;

    int kb = (int)(((long)ITERS * s) / SPLITS);
    int ke = (int)(((long)ITERS * (s + 1)) / SPLITS);

    int pb = p * PAIRU;                 // pair ring base (u32)

    // ---- pair-local cp.async: 4 x 16B per thread per chunk (4KB/pair) ----
    // op u: gmem row = p*32 + (tp>>3) + 8u ; smem row = (tp>>3) + 8u
    const float* wp0 = Wp + (size_t)(k0 + p * 32 + (tp >> 3)) * KIJ + (tp & 7) * 4;
    uint32_t smoff0 = (uint32_t)(((tp >> 3) * BSTRP + (tp & 7) * 4) * 4);
    uint32_t bs_addr = smem_u32(smem) + (uint32_t)pb * 4u;

#define BARP() asm volatile("bar.sync %0, 64;" :: "r"(p + 1) : "memory")

#define CPY(chunk, stg)                                                       \
    do {                                                                      \
        if ((chunk) < ke) {                                                   \
            size_t off_ = (size_t)((chunk) & 511) * 512 +                     \
                          (size_t)((chunk) >> 9) * 32;                        \
            uint32_t sa_ = bs_addr + (uint32_t)((stg) * (STGP * 4)) + smoff0; \
            const float* gp_ = wp0 + off_;                                    \
            _Pragma("unroll") for (int u_ = 0; u_ < 4; ++u_) {                \
                asm volatile("cp.async.cg.shared.global [%0], [%1], 16;"      \
                             :: "r"(sa_ + u_ * (8 * BSTRP * 4)),              \
                                "l"(gp_ + (size_t)u_ * 8 * KIJ));             \
            }                                                                 \
        }                                                                     \
        asm volatile("cp.async.commit_group;" ::: "memory");                  \
    } while (0)

    int arow[8];
#pragma unroll
    for (int f = 0; f < 4; ++f) {
        arow[2 * f] = wm * 64 + f * 16 + (lane >> 2);
        arow[2 * f + 1] = arow[2 * f] + 8;
    }

    // ---- prologue ----
    CPY(kb, 0);
    CPY(kb + 1, 1);
    CPY(kb + 2, 2);
    CPY(kb + 3, 3);

    uint32_t im_a[8], im_b[8];
    {
        int i0 = kb & 511;
#pragma unroll
        for (int h = 0; h < 8; ++h) im_a[h] = g_imgu[i0 * 256 + b0 + arow[h]];
    }

    float acc[4][4][4];
#pragma unroll
    for (int f = 0; f < 4; ++f)
#pragma unroll
        for (int g = 0; g < 4; ++g)
#pragma unroll
            for (int e = 0; e < 4; ++e) acc[f][g][e] = 0.f;

    int st = 0, stp = 4;
    int c = kb;

    // ---- segmented main loop: txt in registers per j-block ----
#pragma unroll 1
    while (c < ke) {
        int jb = c >> 9;
        int seg_end = (jb + 1) << 9;
        if (seg_end > ke) seg_end = ke;

        // hoist txt operands straight from gmem (u32 = bf16 pair), rare
        uint32_t treg[2][4][4];
        {
            const uint32_t* tb = reinterpret_cast<const uint32_t*>(g_txtb);
#pragma unroll
            for (int k2 = 0; k2 < 2; ++k2) {
                int co = jb * 16 + k2 * 8 + (lane & 3);
#pragma unroll
                for (int f = 0; f < 4; ++f) {
                    const uint32_t* r0 = tb + (size_t)(b0 + arow[2 * f]) * 256;
                    const uint32_t* r1 = tb + (size_t)(b0 + arow[2 * f + 1]) * 256;
                    treg[k2][f][0] = r0[co];
                    treg[k2][f][1] = r1[co];
                    treg[k2][f][2] = r0[co + 4];
                    treg[k2][f][3] = r1[co + 4];
                }
            }
        }

#pragma unroll 1
        for (; c < seg_end; ++c) {
            asm volatile("cp.async.wait_group 3;" ::: "memory");
            BARP();                         // partner's chunk c arrived too

            CPY(c + 4, stp);

            {   // img prefetch for c+1 (address always valid)
                int i1 = (c + 1) & 511;
#pragma unroll
                for (int h = 0; h < 8; ++h)
                    im_b[h] = g_imgu[i1 * 256 + b0 + arow[h]];
            }

            // ---- compute chunk c ----
            {
                const float* bsf = Bsf + pb + st * STGP;
#pragma unroll
                for (int k2 = 0; k2 < 2; ++k2) {
                    uint32_t a[4][4];
#pragma unroll
                    for (int f = 0; f < 4; ++f) {
                        a[f][0] = hmul2u(treg[k2][f][0], im_a[2 * f]);
                        a[f][1] = hmul2u(treg[k2][f][1], im_a[2 * f + 1]);
                        a[f][2] = hmul2u(treg[k2][f][2], im_a[2 * f]);
                        a[f][3] = hmul2u(treg[k2][f][3], im_a[2 * f + 1]);
                    }
                    uint32_t bb[4][2];
#pragma unroll
                    for (int g = 0; g < 4; ++g) {
                        int nloc = g * 8 + (lane >> 2);
                        const float* pf = bsf + nloc * BSTRP + k2 * 16 + (lane & 3) * 2;
                        float2 v0 = *reinterpret_cast<const float2*>(pf);
                        float2 v1 = *reinterpret_cast<const float2*>(pf + 8);
                        bb[g][0] = bpack(v0.x, v0.y);
                        bb[g][1] = bpack(v1.x, v1.y);
                    }
#pragma unroll
                    for (int f = 0; f < 4; ++f)
#pragma unroll
                        for (int g = 0; g < 4; ++g) mma16816(acc[f][g], a[f], bb[g]);
                }
            }

#pragma unroll
            for (int h = 0; h < 8; ++h) im_a[h] = im_b[h];

            st = (st == NSTG - 1) ? 0 : st + 1;
            stp = (stp == NSTG - 1) ? 0 : stp + 1;
        }
    }
    asm volatile("cp.async.wait_group 0;" ::: "memory");

    // ---- split-K epilogue ----
#pragma unroll
    for (int f = 0; f < 4; ++f)
#pragma unroll
        for (int g = 0; g < 4; ++g)
#pragma unroll
            for (int e = 0; e < 4; ++e) {
                int rr = b0 + wm * 64 + f * 16 + (lane >> 2) + ((e >> 1) << 3);
                int cc = k0 + p * 32 + g * 8 + ((lane & 3) << 1) + (e & 1);
                atomicAdd(&g_feats[rr * 512 + cc], acc[f][g][e]);
            }
#undef CPY
#undef BARP
}

// ------------------ stage 4: bias + relu + classifier + sigmoid -------------
// float4 everywhere: 3x LDG.128 per thread, MLP 4x higher than scalar version
__global__ __launch_bounds__(128) void final_k(const float* __restrict__ bp,
                                               const float* __restrict__ Wc,
                                               const float* __restrict__ bc,
                                               float* __restrict__ out) {
    int b = blockIdx.x;
    int t = threadIdx.x;
    float4 f4 = reinterpret_cast<const float4*>(g_feats + b * 512)[t];
    float4 b4 = reinterpret_cast<const float4*>(bp)[t];
    float4 w4 = reinterpret_cast<const float4*>(Wc)[t];
    float p = fmaxf(f4.x + b4.x, 0.f) * w4.x
            + fmaxf(f4.y + b4.y, 0.f) * w4.y
            + fmaxf(f4.z + b4.z, 0.f) * w4.z
            + fmaxf(f4.w + b4.w, 0.f) * w4.w;
#pragma unroll
    for (int o = 16; o > 0; o >>= 1) p += __shfl_xor_sync(0xffffffffu, p, o);
    __shared__ float sr[4];
    if ((t & 31) == 0) sr[t >> 5] = p;
    __syncthreads();
    if (t == 0) {
        float logit = sr[0] + sr[1] + sr[2] + sr[3] + bc[0];
        out[b] = 1.f / (1.f + expf(-logit));
    }
}

// ------------------------------ launcher ------------------------------------
extern "C" void kernel_launch(void* const* d_in, const int* in_sizes, int n_in,
                              void* d_out, int out_size) {
    const float* img_e = (const float*)d_in[0];
    const float* txt_e = (const float*)d_in[1];
    const float* Wi = (const float*)d_in[2];
    const float* bi = (const float*)d_in[3];
    const float* Wt = (const float*)d_in[4];
    const float* bt = (const float*)d_in[5];
    const float* Wp = (const float*)d_in[6];
    const float* bp = (const float*)d_in[7];
    const float* Wc = (const float*)d_in[8];
    const float* bc = (const float*)d_in[9];
    float* out = (float*)d_out;

    cudaFuncSetAttribute(bilinear_gemm, cudaFuncAttributeMaxDynamicSharedMemorySize,
                         SM_BYTES);

    map_gemm2<<<dim3(16, 8, 2), 256>>>(img_e, txt_e, Wi, bi, Wt, bt);
    norm_zero2<<<256, 256>>>();
    bilinear_gemm<<<dim3(SPLITS, 4, 2), 256, SM_BYTES>>>(Wp);
    final_k<<<256, 128>>>(bp, Wc, bc, out);
}